// round 3
// baseline (speedup 1.0000x reference)
#include <cuda_runtime.h>
#include <cuda_bf16.h>

#define CIN 16
#define COUT 32
#define K2 9
#define MAXN 2000000

// Intermediate h1 = relu(conv1(x)) : [N, 32] fp32 (256 MB scratch).
__device__ float g_h1[(size_t)MAXN * COUT];

typedef unsigned long long ull;

__device__ __forceinline__ ull pack2(float a, float b) {
    ull r; asm("mov.b64 %0, {%1, %2};" : "=l"(r) : "f"(a), "f"(b)); return r;
}
__device__ __forceinline__ float2 unpack2(ull v) {
    float2 f; asm("mov.b64 {%0, %1}, %2;" : "=f"(f.x), "=f"(f.y) : "l"(v)); return f;
}
__device__ __forceinline__ ull fma2(ull a, ull b, ull c) {
    ull d; asm("fma.rn.f32x2 %0, %1, %2, %3;" : "=l"(d) : "l"(a), "l"(b), "l"(c)); return d;
}

// Tiling: block = 256 threads, tile = 256 voxels x 32 couts.
// Thread (tx,ty): tx in 0..7 -> couts [4*tx, 4*tx+4); ty in 0..31 -> voxels [8*ty, 8*ty+8).
// Warp = 8 tx x 4 ty  (weight LDS broadcast over ty; h LDS conflict-free over ty: banks step 8).

#define S1 258   // xT row stride (floats), conv1 staging conflict-free
#define S2 257   // hT row stride (floats), conv2 staging conflict-free

// =====================================================================
// conv1: h1 = relu( sum_k mask*x[idx] @ W1[k] + b1 )
// =====================================================================
__global__ __launch_bounds__(256)
void conv1_kernel(const float* __restrict__ x,
                  const float* __restrict__ W1,
                  const float* __restrict__ b1,
                  const int* __restrict__ nbr_idx,
                  const unsigned int* __restrict__ nbr_mask,
                  int n) {
    extern __shared__ char smem[];
    float* xT = (float*)smem;                                   // [16][S1]
    ull*   Ws = (ull*)(smem + CIN * S1 * sizeof(float));        // 9*16*16 = 2304
    ull*   bs = Ws + K2 * CIN * (COUT / 2);                     // 16

    // weights -> smem (f32x2 pairs)
    for (int t = threadIdx.x; t < K2 * CIN * (COUT / 2); t += 256) {
        int row = t >> 4, p = t & 15;
        Ws[t] = pack2(W1[row * COUT + 2 * p], W1[row * COUT + 2 * p + 1]);
    }
    if (threadIdx.x < COUT / 2)
        bs[threadIdx.x] = pack2(b1[2 * threadIdx.x], b1[2 * threadIdx.x + 1]);
    __syncthreads();

    const int tx = threadIdx.x & 7;
    const int ty = threadIdx.x >> 3;
    const int v0 = blockIdx.x * 256;

    ull acc[8][2];
    ull bw0 = bs[tx * 2], bw1 = bs[tx * 2 + 1];
#pragma unroll
    for (int vi = 0; vi < 8; vi++) { acc[vi][0] = bw0; acc[vi][1] = bw1; }

    for (int k = 0; k < K2; k++) {
        __syncthreads();   // previous tap's compute done before restaging
        // stage: 256 rows x 4 float4 -> transposed xT[c][row]
#pragma unroll
        for (int i = 0; i < 4; i++) {
            int id  = threadIdx.x + i * 256;
            int row = id >> 2, cq = id & 3;
            int v = v0 + row;
            float4 g = make_float4(0.f, 0.f, 0.f, 0.f);
            if (v < n) {
                size_t off = (size_t)k * n + v;
                if (nbr_mask[off]) {
                    int idx = nbr_idx[off];
                    g = __ldg((const float4*)(x + (size_t)idx * CIN) + cq);
                }
            }
            int c = cq * 4;
            xT[(c + 0) * S1 + row] = g.x;
            xT[(c + 1) * S1 + row] = g.y;
            xT[(c + 2) * S1 + row] = g.z;
            xT[(c + 3) * S1 + row] = g.w;
        }
        __syncthreads();
        const ull* wk = Ws + k * (CIN * (COUT / 2));
#pragma unroll
        for (int c = 0; c < CIN; c++) {
            float h[8];
#pragma unroll
            for (int vi = 0; vi < 8; vi++) h[vi] = xT[c * S1 + ty * 8 + vi];
            ull w0 = wk[c * (COUT / 2) + tx * 2];
            ull w1 = wk[c * (COUT / 2) + tx * 2 + 1];
#pragma unroll
            for (int vi = 0; vi < 8; vi++) {
                ull hh = pack2(h[vi], h[vi]);
                acc[vi][0] = fma2(hh, w0, acc[vi][0]);
                acc[vi][1] = fma2(hh, w1, acc[vi][1]);
            }
        }
    }

    // epilogue: relu -> g_h1, coalesced 16B per thread-voxel
#pragma unroll
    for (int vi = 0; vi < 8; vi++) {
        int v = v0 + ty * 8 + vi;
        if (v < n) {
            float2 a = unpack2(acc[vi][0]), b = unpack2(acc[vi][1]);
            float4 r = make_float4(fmaxf(a.x, 0.f), fmaxf(a.y, 0.f),
                                   fmaxf(b.x, 0.f), fmaxf(b.y, 0.f));
            *((float4*)(g_h1 + (size_t)v * COUT + tx * 4)) = r;
        }
    }
}

// =====================================================================
// conv2 + residual: out = relu( sum_k mask*h1[idx] @ W2[k] + b2 + x @ Wp + bp )
// =====================================================================
__global__ __launch_bounds__(256)
void conv2_kernel(const float* __restrict__ x,
                  const float* __restrict__ W2,
                  const float* __restrict__ b2,
                  const float* __restrict__ Wp,
                  const float* __restrict__ bp,
                  const int* __restrict__ nbr_idx,
                  const unsigned int* __restrict__ nbr_mask,
                  float* __restrict__ out,
                  int n) {
    extern __shared__ char smem[];
    float* hT  = (float*)smem;                                  // [32][S2]
    ull*   Ws2 = (ull*)(smem + COUT * S2 * sizeof(float));      // 9*32*16 = 4608
    ull*   Wps = Ws2 + K2 * COUT * (COUT / 2);                  // 16*16 = 256
    ull*   bs  = Wps + CIN * (COUT / 2);                        // 16

    for (int t = threadIdx.x; t < K2 * COUT * (COUT / 2); t += 256) {
        int row = t >> 4, p = t & 15;
        Ws2[t] = pack2(W2[row * COUT + 2 * p], W2[row * COUT + 2 * p + 1]);
    }
    for (int t = threadIdx.x; t < CIN * (COUT / 2); t += 256) {
        int row = t >> 4, p = t & 15;
        Wps[t] = pack2(Wp[row * COUT + 2 * p], Wp[row * COUT + 2 * p + 1]);
    }
    if (threadIdx.x < COUT / 2)
        bs[threadIdx.x] = pack2(b2[2 * threadIdx.x] + bp[2 * threadIdx.x],
                                b2[2 * threadIdx.x + 1] + bp[2 * threadIdx.x + 1]);
    __syncthreads();

    const int tx = threadIdx.x & 7;
    const int ty = threadIdx.x >> 3;
    const int v0 = blockIdx.x * 256;

    ull acc[8][2];
    ull bw0 = bs[tx * 2], bw1 = bs[tx * 2 + 1];
#pragma unroll
    for (int vi = 0; vi < 8; vi++) { acc[vi][0] = bw0; acc[vi][1] = bw1; }

    // --- residual projection: stage own x rows (contiguous), 16 c-steps ---
    __syncthreads();
#pragma unroll
    for (int i = 0; i < 4; i++) {
        int id  = threadIdx.x + i * 256;
        int row = id >> 2, cq = id & 3;
        int v = v0 + row;
        float4 g = make_float4(0.f, 0.f, 0.f, 0.f);
        if (v < n) g = __ldg((const float4*)(x + (size_t)v * CIN) + cq);
        int c = cq * 4;
        hT[(c + 0) * S2 + row] = g.x;
        hT[(c + 1) * S2 + row] = g.y;
        hT[(c + 2) * S2 + row] = g.z;
        hT[(c + 3) * S2 + row] = g.w;
    }
    __syncthreads();
#pragma unroll
    for (int c = 0; c < CIN; c++) {
        float h[8];
#pragma unroll
        for (int vi = 0; vi < 8; vi++) h[vi] = hT[c * S2 + ty * 8 + vi];
        ull w0 = Wps[c * (COUT / 2) + tx * 2];
        ull w1 = Wps[c * (COUT / 2) + tx * 2 + 1];
#pragma unroll
        for (int vi = 0; vi < 8; vi++) {
            ull hh = pack2(h[vi], h[vi]);
            acc[vi][0] = fma2(hh, w0, acc[vi][0]);
            acc[vi][1] = fma2(hh, w1, acc[vi][1]);
        }
    }

    // --- 9 taps over gathered h1 rows ---
    for (int k = 0; k < K2; k++) {
        __syncthreads();
#pragma unroll
        for (int i = 0; i < 8; i++) {
            int id  = threadIdx.x + i * 256;
            int row = id >> 3, cq = id & 7;
            int v = v0 + row;
            float4 g = make_float4(0.f, 0.f, 0.f, 0.f);
            if (v < n) {
                size_t off = (size_t)k * n + v;
                if (nbr_mask[off]) {
                    int idx = nbr_idx[off];
                    g = __ldg((const float4*)(g_h1 + (size_t)idx * COUT) + cq);
                }
            }
            int c = cq * 4;
            hT[(c + 0) * S2 + row] = g.x;
            hT[(c + 1) * S2 + row] = g.y;
            hT[(c + 2) * S2 + row] = g.z;
            hT[(c + 3) * S2 + row] = g.w;
        }
        __syncthreads();
        const ull* wk = Ws2 + k * (COUT * (COUT / 2));
#pragma unroll
        for (int c = 0; c < COUT; c++) {
            float h[8];
#pragma unroll
            for (int vi = 0; vi < 8; vi++) h[vi] = hT[c * S2 + ty * 8 + vi];
            ull w0 = wk[c * (COUT / 2) + tx * 2];
            ull w1 = wk[c * (COUT / 2) + tx * 2 + 1];
#pragma unroll
            for (int vi = 0; vi < 8; vi++) {
                ull hh = pack2(h[vi], h[vi]);
                acc[vi][0] = fma2(hh, w0, acc[vi][0]);
                acc[vi][1] = fma2(hh, w1, acc[vi][1]);
            }
        }
    }

    // epilogue: relu -> out
#pragma unroll
    for (int vi = 0; vi < 8; vi++) {
        int v = v0 + ty * 8 + vi;
        if (v < n) {
            float2 a = unpack2(acc[vi][0]), b = unpack2(acc[vi][1]);
            float4 r = make_float4(fmaxf(a.x, 0.f), fmaxf(a.y, 0.f),
                                   fmaxf(b.x, 0.f), fmaxf(b.y, 0.f));
            *((float4*)(out + (size_t)v * COUT + tx * 4)) = r;
        }
    }
}

// =====================================================================
// Launch.  Input order: x, W1, b1, W2, b2, Wp, bp, nbr_idx, nbr_mask
// =====================================================================
extern "C" void kernel_launch(void* const* d_in, const int* in_sizes, int n_in,
                              void* d_out, int out_size) {
    const float* x  = (const float*)d_in[0];
    const float* W1 = (const float*)d_in[1];
    const float* b1 = (const float*)d_in[2];
    const float* W2 = (const float*)d_in[3];
    const float* b2 = (const float*)d_in[4];
    const float* Wp = (const float*)d_in[5];
    const float* bp = (const float*)d_in[6];
    const int* nbr_idx = (const int*)d_in[7];
    const unsigned int* nbr_mask = (const unsigned int*)d_in[8];
    float* out = (float*)d_out;

    int n = in_sizes[0] / CIN;
    if (n > MAXN) n = MAXN;

    const int smem1 = CIN * S1 * 4 + (K2 * CIN * (COUT / 2) + COUT / 2) * 8 + 64;
    const int smem2 = COUT * S2 * 4 +
                      (K2 * COUT * (COUT / 2) + CIN * (COUT / 2) + COUT / 2) * 8 + 64;

    static bool attr_done = false;
    if (!attr_done) {
        cudaFuncSetAttribute(conv1_kernel, cudaFuncAttributeMaxDynamicSharedMemorySize, smem1);
        cudaFuncSetAttribute(conv2_kernel, cudaFuncAttributeMaxDynamicSharedMemorySize, smem2);
        attr_done = true;
    }

    int blocks = (n + 255) / 256;
    conv1_kernel<<<blocks, 256, smem1>>>(x, W1, b1, nbr_idx, nbr_mask, n);
    conv2_kernel<<<blocks, 256, smem2>>>(x, W2, b2, Wp, bp, nbr_idx, nbr_mask, out, n);
}